// round 15
// baseline (speedup 1.0000x reference)
#include <cuda_runtime.h>
#include <cstdint>

// Degenerate conv (reference uses only x[:,0] and w[:,2]):
//   out(n,f,i,j) = bias[f] + sum_{a,b} w[f,2,a,b] * x[n,0,i+a,j+b]
//   x: (16,3,256,256) f32, w: (64,3,3,3) f32, b: (64,) f32
//   out: (16,64,254,254) f32
//
// Steady-state bound: 264MB output write at ~5.1 TB/s HBM drain => ~51.5us.
// Kernel geometry (R14 + wrap fusion):
//   grid (127, 16, 4), block 128. rs = tid>>6 row parity, t = tid&63.
//   Even row i=2bx:  lanes t=0..62 store STG.128 at j=4t (cols 0..251);
//                    lane t=63 stores the WRAP: out[i][252..253] +
//                    out[i+1][0..1], one contiguous 16B-aligned STG.128.
//                    Even-row warp span = fully dense 1024B.
//   Odd row i+1:     lanes t=0..62 store STG.128 at j=4t+2 (cols 2..253);
//                    lane t=63 idles. (Row stride 1016B == 8 mod 16 makes
//                    both j-phases 16B-aligned.)
// Weights in __constant__ (uniform LDC port, one CE staging node);
// bias via uniform LDG.128 with static component selects.
#define NB     16
#define F_OUT  64
#define F_Q    16
#define Hh     256
#define Ww     256
#define HO     254
#define WO     254
#define OIMG   (HO * WO)          // 64516

typedef unsigned long long u64;

__constant__ float c_w[F_OUT * 27];   // full weight tensor (we use [f][2][*])

// packed f32x2 FMA (Blackwell): d = a * w + c on both lanes
static __device__ __forceinline__ u64 ffma2(u64 a, u64 w, u64 c) {
    u64 d;
    asm("fma.rn.f32x2 %0, %1, %2, %3;" : "=l"(d) : "l"(a), "l"(w), "l"(c));
    return d;
}

static __device__ __forceinline__ u64 pack2(float lo, float hi) {
    u64 d;
    asm("mov.b64 %0, {%1, %2};" : "=l"(d) : "f"(lo), "f"(hi));
    return d;
}

__global__ __launch_bounds__(128) void conv2dcq_kernel(
    const float* __restrict__ x,
    const float* __restrict__ bias,
    float* __restrict__ out) {

    const int tid = threadIdx.x;
    const int rs  = tid >> 6;             // row parity, warp-uniform
    const int t   = tid & 63;             // col tile 0..63
    const int n   = blockIdx.y;
    const int f0  = blockIdx.z * F_Q;     // block-uniform filter base
    const int i   = blockIdx.x * 2 + rs;  // output row (even for rs=0)

    const float* xim = x + (size_t)n * 3 * Hh * Ww;        // channel 0
    float* oimg = out + (size_t)n * F_OUT * OIMG + (size_t)f0 * OIMG;

    // bias for this quarter: 4 uniform LDG.128 (64B-aligned)
    const float4* b4 = reinterpret_cast<const float4*>(bias + f0);

    if (t < 63) {
        // ================= main: STG.128 tiles =================
        const int j = 4 * t + 2 * rs;         // 16B-aligned store col

        const float* xrow = xim + (size_t)i * Ww;

        // P[r][s] = (x[i+r][j+s], x[i+r][j+s+1]), r=0..2, s=0..4
        u64 P[3][5];
        if (rs == 0) {                        // warp-uniform branch
            #pragma unroll
            for (int r = 0; r < 3; r++) {
                const float* xr = xrow + (size_t)r * Ww + j;
                const float4 a = *reinterpret_cast<const float4*>(xr);
                const float2 b = *reinterpret_cast<const float2*>(xr + 4);
                P[r][0] = pack2(a.x, a.y);
                P[r][1] = pack2(a.y, a.z);
                P[r][2] = pack2(a.z, a.w);
                P[r][3] = pack2(a.w, b.x);
                P[r][4] = pack2(b.x, b.y);
            }
        } else {
            #pragma unroll
            for (int r = 0; r < 3; r++) {
                const float* xr = xrow + (size_t)r * Ww + j;
                const float2 a = *reinterpret_cast<const float2*>(xr);
                const float4 b = *reinterpret_cast<const float4*>(xr + 2);
                P[r][0] = pack2(a.x, a.y);
                P[r][1] = pack2(a.y, b.x);
                P[r][2] = pack2(b.x, b.y);
                P[r][3] = pack2(b.y, b.z);
                P[r][4] = pack2(b.z, b.w);
            }
        }

        float* ob = oimg + (size_t)i * WO + j;

        #pragma unroll
        for (int g = 0; g < 4; g++) {
            const float4 bq = __ldg(b4 + g);              // uniform LDG.128
            const float bsel[4] = {bq.x, bq.y, bq.z, bq.w};

            #pragma unroll
            for (int u = 0; u < 4; u++) {                 // static select only
                const int f = f0 + g * 4 + u;
                const float* wf = c_w + f * 27 + 18;      // uniform LDC
                const float bv = bsel[u];
                u64 a0 = pack2(bv, bv);   // cols j, j+1
                u64 a1 = a0;              // cols j+2, j+3

                #pragma unroll
                for (int a = 0; a < 3; a++) {
                    #pragma unroll
                    for (int b = 0; b < 3; b++) {
                        const float ws = wf[a * 3 + b];   // constant port
                        const u64 wp = pack2(ws, ws);
                        a0 = ffma2(P[a][b],     wp, a0);
                        a1 = ffma2(P[a][b + 2], wp, a1);
                    }
                }

                // (1016*i + 4*j) % 16 == 0 by construction
                *reinterpret_cast<ulonglong2*>(ob) = make_ulonglong2(a0, a1);
                ob += (size_t)OIMG;
            }
        }
    } else if (rs == 0) {
        // ================= wrap lane (tid 63): ragged edges =================
        // out[i][252..253] (right edge, even row i) and out[i+1][0..1]
        // (left edge, odd row) are CONTIGUOUS + 16B-aligned in memory
        // -> one STG.128 per filter covers both.
        // Right-edge inputs: rows i..i+2, cols 252..255 (float4 @ 1008B ok)
        // Left-edge inputs:  rows i+1..i+3, cols 0..3
        u64 PR[3][3], PL[3][3];
        #pragma unroll
        for (int r = 0; r < 3; r++) {
            const float4 a = *reinterpret_cast<const float4*>(
                xim + (size_t)(i + r) * Ww + 252);
            PR[r][0] = pack2(a.x, a.y);
            PR[r][1] = pack2(a.y, a.z);
            PR[r][2] = pack2(a.z, a.w);
            const float4 c = *reinterpret_cast<const float4*>(
                xim + (size_t)(i + 1 + r) * Ww);
            PL[r][0] = pack2(c.x, c.y);
            PL[r][1] = pack2(c.y, c.z);
            PL[r][2] = pack2(c.z, c.w);
        }

        // byte offset 1016*i + 1008 ≡ 0 mod 16 (i even)
        float* ob = oimg + (size_t)i * WO + 252;

        #pragma unroll
        for (int g = 0; g < 4; g++) {
            const float4 bq = __ldg(b4 + g);
            const float bsel[4] = {bq.x, bq.y, bq.z, bq.w};

            #pragma unroll
            for (int u = 0; u < 4; u++) {
                const int f = f0 + g * 4 + u;
                const float* wf = c_w + f * 27 + 18;
                const float bv = bsel[u];
                u64 aR = pack2(bv, bv);   // out[i][252..253]
                u64 aL = aR;              // out[i+1][0..1]

                #pragma unroll
                for (int a = 0; a < 3; a++) {
                    #pragma unroll
                    for (int b = 0; b < 3; b++) {
                        const float ws = wf[a * 3 + b];
                        const u64 wp = pack2(ws, ws);
                        aR = ffma2(PR[a][b], wp, aR);
                        aL = ffma2(PL[a][b], wp, aL);
                    }
                }

                *reinterpret_cast<ulonglong2*>(ob) = make_ulonglong2(aR, aL);
                ob += (size_t)OIMG;
            }
        }
    }
    // tid 127 (rs==1, t==63): no work
}

extern "C" void kernel_launch(void* const* d_in, const int* in_sizes, int n_in,
                              void* d_out, int out_size) {
    const float* x    = (const float*)d_in[0];
    const float* w    = (const float*)d_in[1];
    const float* bias = (const float*)d_in[2];
    float* out        = (float*)d_out;

    // Single CE node: stage weights into constant memory (D2D, capturable).
    cudaMemcpyToSymbolAsync(c_w, w, F_OUT * 27 * sizeof(float), 0,
                            cudaMemcpyDeviceToDevice, 0);

    dim3 grid(HO / 2, NB, F_OUT / F_Q);   // (127, 16, 4) -- no strip blocks
    conv2dcq_kernel<<<grid, 128>>>(x, bias, out);
}

// round 16
// speedup vs baseline: 1.0719x; 1.0719x over previous
#include <cuda_runtime.h>
#include <cstdint>

// Degenerate conv (reference uses only x[:,0] and w[:,2]):
//   out(n,f,i,j) = bias[f] + sum_{a,b} w[f,2,a,b] * x[n,0,i+a,j+b]
//   x: (16,3,256,256) f32, w: (64,3,3,3) f32, b: (64,) f32
//   out: (16,64,254,254) f32
//
// Steady-state bound: 264MB output write at ~5.1 TB/s HBM drain => ~51.7us
// (confirmed across 4 distinct kernel structures). This round tests the one
// untested lever: st.global.cs (evict-first) on the otherwise-champion R14
// geometry, to keep the streamed output from thrashing the input set in L2.
//
// Geometry (== R14): main blocks (bx < 127): 1 row x 4 cols per thread
// (t=0..62), 16 filters, all stores 16B-aligned warp-dense STG.128; even
// rows at j=4t, odd rows at j=4t+2. Strip block (bx==127): for row-pair ip,
// out[2ip][252..253] + out[2ip+1][0..1] are contiguous + 16B-aligned ->
// one STG.128 per filter. Weights in __constant__; bias uniform LDG.128.
#define NB     16
#define F_OUT  64
#define F_Q    16
#define Hh     256
#define Ww     256
#define HO     254
#define WO     254
#define OIMG   (HO * WO)          // 64516

typedef unsigned long long u64;

__constant__ float c_w[F_OUT * 27];   // full weight tensor (we use [f][2][*])

// packed f32x2 FMA (Blackwell): d = a * w + c on both lanes
static __device__ __forceinline__ u64 ffma2(u64 a, u64 w, u64 c) {
    u64 d;
    asm("fma.rn.f32x2 %0, %1, %2, %3;" : "=l"(d) : "l"(a), "l"(w), "l"(c));
    return d;
}

static __device__ __forceinline__ u64 pack2(float lo, float hi) {
    u64 d;
    asm("mov.b64 %0, {%1, %2};" : "=l"(d) : "f"(lo), "f"(hi));
    return d;
}

// evict-first 16B store: output is write-once stream, don't hold it in L2
static __device__ __forceinline__ void stcs128(float* p, u64 a, u64 b) {
    asm volatile("st.global.cs.v2.b64 [%0], {%1, %2};"
                 :: "l"(p), "l"(a), "l"(b) : "memory");
}

__global__ __launch_bounds__(128) void conv2dcq_kernel(
    const float* __restrict__ x,
    const float* __restrict__ bias,
    float* __restrict__ out) {

    const int tid = threadIdx.x;
    const int n   = blockIdx.y;
    const int f0  = blockIdx.z * F_Q;     // block-uniform filter base

    const float* xim = x + (size_t)n * 3 * Hh * Ww;        // channel 0
    float* oimg = out + (size_t)n * F_OUT * OIMG + (size_t)f0 * OIMG;

    // bias for this quarter: 4 uniform LDG.128 (64B-aligned)
    const float4* b4 = reinterpret_cast<const float4*>(bias + f0);

    if (blockIdx.x < 127) {
        // ================= main: STG.128 tiles, t = 0..62 only =============
        const int rs = tid >> 6;              // row parity, warp-uniform
        const int t  = tid & 63;              // col tile 0..63
        if (t >= 63) return;                  // coverage guard

        const int i  = blockIdx.x * 2 + rs;   // output row
        const int j  = 4 * t + 2 * rs;        // 16B-aligned store col

        const float* xrow = xim + (size_t)i * Ww;

        // P[r][s] = (x[i+r][j+s], x[i+r][j+s+1]), r=0..2, s=0..4
        u64 P[3][5];
        if (rs == 0) {                        // warp-uniform branch
            #pragma unroll
            for (int r = 0; r < 3; r++) {
                const float* xr = xrow + (size_t)r * Ww + j;
                const float4 a = *reinterpret_cast<const float4*>(xr);
                const float2 b = *reinterpret_cast<const float2*>(xr + 4);
                P[r][0] = pack2(a.x, a.y);
                P[r][1] = pack2(a.y, a.z);
                P[r][2] = pack2(a.z, a.w);
                P[r][3] = pack2(a.w, b.x);
                P[r][4] = pack2(b.x, b.y);
            }
        } else {
            #pragma unroll
            for (int r = 0; r < 3; r++) {
                const float* xr = xrow + (size_t)r * Ww + j;
                const float2 a = *reinterpret_cast<const float2*>(xr);
                const float4 b = *reinterpret_cast<const float4*>(xr + 2);
                P[r][0] = pack2(a.x, a.y);
                P[r][1] = pack2(a.y, b.x);
                P[r][2] = pack2(b.x, b.y);
                P[r][3] = pack2(b.y, b.z);
                P[r][4] = pack2(b.z, b.w);
            }
        }

        float* ob = oimg + (size_t)i * WO + j;

        #pragma unroll
        for (int g = 0; g < 4; g++) {
            const float4 bq = __ldg(b4 + g);              // uniform LDG.128
            const float bsel[4] = {bq.x, bq.y, bq.z, bq.w};

            #pragma unroll
            for (int u = 0; u < 4; u++) {                 // static select only
                const int f = f0 + g * 4 + u;
                const float* wf = c_w + f * 27 + 18;      // uniform LDC
                const float bv = bsel[u];
                u64 a0 = pack2(bv, bv);   // cols j, j+1
                u64 a1 = a0;              // cols j+2, j+3

                #pragma unroll
                for (int a = 0; a < 3; a++) {
                    #pragma unroll
                    for (int b = 0; b < 3; b++) {
                        const float ws = wf[a * 3 + b];   // constant port
                        const u64 wp = pack2(ws, ws);
                        a0 = ffma2(P[a][b],     wp, a0);
                        a1 = ffma2(P[a][b + 2], wp, a1);
                    }
                }

                // (1016*i + 4*j) % 16 == 0 by construction
                stcs128(ob, a0, a1);
                ob += (size_t)OIMG;
            }
        }
    } else {
        // ================= strip: ragged edges, one STG.128/filter =========
        const int ip = tid;
        if (ip >= 127) return;
        const int i = ip * 2;

        u64 PR[3][3], PL[3][3];
        #pragma unroll
        for (int r = 0; r < 3; r++) {
            const float4 a = *reinterpret_cast<const float4*>(
                xim + (size_t)(i + r) * Ww + 252);
            PR[r][0] = pack2(a.x, a.y);
            PR[r][1] = pack2(a.y, a.z);
            PR[r][2] = pack2(a.z, a.w);
            const float4 c = *reinterpret_cast<const float4*>(
                xim + (size_t)(i + 1 + r) * Ww);
            PL[r][0] = pack2(c.x, c.y);
            PL[r][1] = pack2(c.y, c.z);
            PL[r][2] = pack2(c.z, c.w);
        }

        // out[i][252..253] + out[i+1][0..1]: contiguous, 16B-aligned (i even)
        float* ob = oimg + (size_t)i * WO + 252;

        #pragma unroll
        for (int g = 0; g < 4; g++) {
            const float4 bq = __ldg(b4 + g);
            const float bsel[4] = {bq.x, bq.y, bq.z, bq.w};

            #pragma unroll
            for (int u = 0; u < 4; u++) {
                const int f = f0 + g * 4 + u;
                const float* wf = c_w + f * 27 + 18;
                const float bv = bsel[u];
                u64 aR = pack2(bv, bv);   // out[i][252..253]
                u64 aL = aR;              // out[i+1][0..1]

                #pragma unroll
                for (int a = 0; a < 3; a++) {
                    #pragma unroll
                    for (int b = 0; b < 3; b++) {
                        const float ws = wf[a * 3 + b];
                        const u64 wp = pack2(ws, ws);
                        aR = ffma2(PR[a][b], wp, aR);
                        aL = ffma2(PL[a][b], wp, aL);
                    }
                }

                stcs128(ob, aR, aL);
                ob += (size_t)OIMG;
            }
        }
    }
}

extern "C" void kernel_launch(void* const* d_in, const int* in_sizes, int n_in,
                              void* d_out, int out_size) {
    const float* x    = (const float*)d_in[0];
    const float* w    = (const float*)d_in[1];
    const float* bias = (const float*)d_in[2];
    float* out        = (float*)d_out;

    // Single CE node: stage weights into constant memory (D2D, capturable).
    cudaMemcpyToSymbolAsync(c_w, w, F_OUT * 27 * sizeof(float), 0,
                            cudaMemcpyDeviceToDevice, 0);

    dim3 grid(128, NB, F_OUT / F_Q);   // (127 main + 1 strip, 16, 4)
    conv2dcq_kernel<<<grid, 128>>>(x, bias, out);
}